// round 5
// baseline (speedup 1.0000x reference)
#include <cuda_runtime.h>
#include <cuda_bf16.h>

#define THREADS     256
#define PER_THREAD  8          // float4-pairs per thread on the fast path
#define SCALE       4194304.0  // 2^22 fixed-point scale for deterministic u64 accumulation

__device__ unsigned long long g_sum;
__device__ unsigned int       g_count;

__device__ __forceinline__ float poly_elem(float x, float t) {
    // t is exactly 0.0 or 1.0. pt = sigmoid(t>0 ? x : -x), clipped symmetric.
    float xp = (t > 0.0f) ? x : -x;
    float pt = __fdividef(1.0f, 1.0f + __expf(-xp));
    pt = fminf(fmaxf(pt, 1.0e-4f), 1.0f - 1.0e-4f);
    // poly = -log(pt) + 2*(1 - pt); the -100 log clamp never fires after the clip.
    return fmaf(-2.0f, pt, 2.0f) - __logf(pt);
}

__device__ __forceinline__ float poly4(float4 xv, float4 tv) {
    return (poly_elem(xv.x, tv.x) + poly_elem(xv.y, tv.y))
         + (poly_elem(xv.z, tv.z) + poly_elem(xv.w, tv.w));
}

__device__ __forceinline__ float block_reduce_sum(float val) {
    #pragma unroll
    for (int o = 16; o > 0; o >>= 1)
        val += __shfl_down_sync(0xffffffffu, val, o);
    __shared__ float sh[32];
    int lane = threadIdx.x & 31;
    int wid  = threadIdx.x >> 5;
    if (lane == 0) sh[wid] = val;
    __syncthreads();
    int nwarps = blockDim.x >> 5;
    val = (threadIdx.x < nwarps) ? sh[lane] : 0.0f;
    if (wid == 0) {
        #pragma unroll
        for (int o = 16; o > 0; o >>= 1)
            val += __shfl_down_sync(0xffffffffu, val, o);
    }
    return val;
}

__device__ __forceinline__ void epilogue(float bs,
                                         const float* __restrict__ cls_preds,
                                         const float* __restrict__ cls_gts,
                                         float* __restrict__ out,
                                         int n_hm, int B) {
    __shared__ bool is_last;
    if (threadIdx.x == 0) {
        long long q = llrint((double)bs * SCALE);  // bs >= 0 always
        atomicAdd(&g_sum, (unsigned long long)q);
        __threadfence();
        unsigned int prev = atomicAdd(&g_count, 1u);
        is_last = (prev == gridDim.x - 1u);
    }
    __syncthreads();

    if (is_last) {
        float c = 0.0f;
        for (int i = threadIdx.x; i < B; i += blockDim.x) {
            float p = cls_preds[i];
            float g = cls_gts[i];
            float logp   = fmaxf(logf(p), -100.0f);
            float log1mp = fmaxf(logf(1.0f - p), -100.0f);
            c += -(g * logp + (1.0f - g) * log1mp);
        }
        __syncthreads();
        float cs = block_reduce_sum(c);
        if (threadIdx.x == 0) {
            __threadfence();
            double total = (double)(long long)g_sum / SCALE;
            out[0] = (float)(total / (double)n_hm);
            out[1] = (cs / (float)B) * 0.05f;
            g_sum   = 0ull;
            g_count = 0u;
        }
    }
}

// Fast path: n4 == gridDim.x * THREADS * PER_THREAD exactly.
// Two groups of 4 float4-pairs: 8 front-batched LDG.128 per group,
// 4 independent accumulators to break the FP dependency chain.
__global__ void __launch_bounds__(THREADS)
poly_loss_fast_kernel(const float4* __restrict__ x4,
                      const float4* __restrict__ t4,
                      const float*  __restrict__ cls_preds,
                      const float*  __restrict__ cls_gts,
                      float*        __restrict__ out,
                      int n_hm, int B) {
    const int T   = gridDim.x * THREADS;
    const int tid = blockIdx.x * THREADS + threadIdx.x;

    float s0 = 0.0f, s1 = 0.0f, s2 = 0.0f, s3 = 0.0f;
    #pragma unroll
    for (int k = 0; k < PER_THREAD / 4; ++k) {
        int b = tid + (4 * k) * T;
        float4 x0 = x4[b];
        float4 x1 = x4[b + T];
        float4 x2 = x4[b + 2 * T];
        float4 x3 = x4[b + 3 * T];
        float4 t0 = t4[b];
        float4 t1 = t4[b + T];
        float4 t2 = t4[b + 2 * T];
        float4 t3 = t4[b + 3 * T];
        s0 += poly4(x0, t0);
        s1 += poly4(x1, t1);
        s2 += poly4(x2, t2);
        s3 += poly4(x3, t3);
    }
    float bs = block_reduce_sum((s0 + s1) + (s2 + s3));
    epilogue(bs, cls_preds, cls_gts, out, n_hm, B);
}

// Generic fallback: plain grid-stride.
__global__ void __launch_bounds__(THREADS)
poly_loss_generic_kernel(const float4* __restrict__ x4,
                         const float4* __restrict__ t4,
                         const float*  __restrict__ cls_preds,
                         const float*  __restrict__ cls_gts,
                         float*        __restrict__ out,
                         int n4, int n_hm, int B) {
    float sum = 0.0f;
    int stride = gridDim.x * blockDim.x;
    for (int i = blockIdx.x * blockDim.x + threadIdx.x; i < n4; i += stride) {
        float4 xv = x4[i];
        float4 tv = t4[i];
        sum += poly4(xv, tv);
    }
    float bs = block_reduce_sum(sum);
    epilogue(bs, cls_preds, cls_gts, out, n_hm, B);
}

extern "C" void kernel_launch(void* const* d_in, const int* in_sizes, int n_in,
                              void* d_out, int out_size) {
    const float* hm_outputs = (const float*)d_in[0];
    const float* hm_targets = (const float*)d_in[1];
    const float* cls_preds  = (const float*)d_in[2];
    const float* cls_gts    = (const float*)d_in[3];
    float* out = (float*)d_out;

    int n_hm = in_sizes[0];           // B*C*H*W = 9,437,184
    int B    = in_sizes[2];           // 64
    int n4   = n_hm >> 2;             // divisible by 4

    const int chunk = THREADS * PER_THREAD;   // 2048 float4-pairs per block
    if ((n_hm & 3) == 0 && (n4 % chunk) == 0) {
        int blocks = n4 / chunk;              // 1152 for the reference shape
        poly_loss_fast_kernel<<<blocks, THREADS>>>(
            (const float4*)hm_outputs, (const float4*)hm_targets,
            cls_preds, cls_gts, out, n_hm, B);
    } else {
        poly_loss_generic_kernel<<<1184, THREADS>>>(
            (const float4*)hm_outputs, (const float4*)hm_targets,
            cls_preds, cls_gts, out, n4, n_hm, B);
    }
}